// round 11
// baseline (speedup 1.0000x reference)
#include <cuda_runtime.h>

#define T_STEPS 2048
#define BATCH   256
#define DIN     128
#define NG      16
#define RDEPTH  4

// Scratch: per (t, b, unit u): {cos(zx) for gates 0..3, sin(zx) for gates 0..3}
// layout: float8 at index ((t*BATCH + b)*4 + u), over-allocated by RDEPTH steps.
__device__ float g_xproj[(size_t)(T_STEPS + RDEPTH) * BATCH * 32];

// ---------------------------------------------------------------------------
// Kernel 1: fused 4-gate projection + sincos precompute
// ---------------------------------------------------------------------------
#define TILE_ROWS    64
#define PROJ_THREADS 256

__global__ __launch_bounds__(PROJ_THREADS)
void proj_kernel(const float* __restrict__ x,
                 const float* __restrict__ Wf, const float* __restrict__ bf, const float* __restrict__ thf,
                 const float* __restrict__ Wi, const float* __restrict__ bi, const float* __restrict__ thi,
                 const float* __restrict__ Wu, const float* __restrict__ bu, const float* __restrict__ thu,
                 const float* __restrict__ Wo, const float* __restrict__ bo, const float* __restrict__ tho)
{
    __shared__ float xs[TILE_ROWS][132];
    __shared__ float ws[DIN][NG];          // ws[j][u*4+g]
    __shared__ float bt[NG];

    const int tid = threadIdx.x;
    const long rowBase = (long)blockIdx.x * TILE_ROWS;

    const float4* x4 = (const float4*)x + rowBase * (DIN / 4);
    #pragma unroll
    for (int i = tid; i < TILE_ROWS * (DIN / 4); i += PROJ_THREADS) {
        float4 v = x4[i];
        int row = i >> 5;
        int c4  = i & 31;
        *(float4*)&xs[row][c4 * 4] = v;
    }
    // stage W transposed: k = u*4 + g
    for (int i = tid; i < DIN * NG; i += PROJ_THREADS) {
        int j = i >> 4, k = i & 15;
        int u = k >> 2, g = k & 3;
        const float* W = (g == 0) ? Wf : (g == 1) ? Wi : (g == 2) ? Wu : Wo;
        ws[j][k] = W[j * 4 + u];
    }
    if (tid < NG) {
        int u = tid >> 2, g = tid & 3;
        const float* b  = (g == 0) ? bf  : (g == 1) ? bi  : (g == 2) ? bu  : bo;
        const float* th = (g == 0) ? thf : (g == 1) ? thi : (g == 2) ? thu : tho;
        bt[tid] = b[u] + th[u];
    }
    __syncthreads();

    const int r = tid & (TILE_ROWS - 1);
    const int u = tid >> 6;                 // unit handled by this thread
    float a0 = 0.f, a1 = 0.f, a2 = 0.f, a3 = 0.f;

    #pragma unroll
    for (int jj = 0; jj < DIN / 4; jj++) {
        float4 xv = *(const float4*)&xs[r][jj * 4];
        float4 w0 = *(const float4*)&ws[jj * 4 + 0][u * 4];
        float4 w1 = *(const float4*)&ws[jj * 4 + 1][u * 4];
        float4 w2 = *(const float4*)&ws[jj * 4 + 2][u * 4];
        float4 w3 = *(const float4*)&ws[jj * 4 + 3][u * 4];
        a0 = fmaf(xv.x, w0.x, fmaf(xv.y, w1.x, fmaf(xv.z, w2.x, fmaf(xv.w, w3.x, a0))));
        a1 = fmaf(xv.x, w0.y, fmaf(xv.y, w1.y, fmaf(xv.z, w2.y, fmaf(xv.w, w3.y, a1))));
        a2 = fmaf(xv.x, w0.z, fmaf(xv.y, w1.z, fmaf(xv.z, w2.z, fmaf(xv.w, w3.z, a2))));
        a3 = fmaf(xv.x, w0.w, fmaf(xv.y, w1.w, fmaf(xv.z, w2.w, fmaf(xv.w, w3.w, a3))));
    }
    float z0 = a0 + bt[u * 4 + 0];
    float z1 = a1 + bt[u * 4 + 1];
    float z2 = a2 + bt[u * 4 + 2];
    float z3 = a3 + bt[u * 4 + 3];

    float4 cq, sq;
    __sincosf(z0, &sq.x, &cq.x);
    __sincosf(z1, &sq.y, &cq.y);
    __sincosf(z2, &sq.z, &cq.z);
    __sincosf(z3, &sq.w, &cq.w);

    float4* dst = (float4*)g_xproj + ((size_t)(rowBase + r) * 4 + u) * 2;
    dst[0] = cq;
    dst[1] = sq;
}

// ---------------------------------------------------------------------------
// Kernel 2: recurrence; 4 lanes per batch element (lane owns hidden unit u)
// cos via angle-addition Horner (FMA pipe only); MUFU only for the 2 tanh.
// ---------------------------------------------------------------------------
__device__ __forceinline__ float tanh_a(float x) {
    float y;
    asm("tanh.approx.f32 %0, %1;" : "=f"(y) : "f"(x));
    return y;
}
// sigmoid on [-1,1] via odd Taylor poly (err <= ~3e-6): fixed-latency FMA chain
__device__ __forceinline__ float sigp(float xv) {
    float x2 = xv * xv;
    float t = fmaf(x2, 2.135765e-5f, -2.1081349e-4f);
    t = fmaf(x2, t, 2.0833333e-3f);
    t = fmaf(x2, t, -2.0833333e-2f);
    t = fmaf(x2, t, 0.25f);
    return fmaf(xv, t, 0.5f);
}
// cos(zx + d) for small |d| (<= 0.35): degree-5 Horner with precomputed cx, sx
__device__ __forceinline__ float cos_aa(float d, float cx, float sx) {
    float p2 = cx * (-0.5f);
    float p3 = sx * (1.0f / 6.0f);
    float p4 = cx * (1.0f / 24.0f);
    float p5 = sx * (-1.0f / 120.0f);
    float t = fmaf(d, p5, p4);
    t = fmaf(d, t, p3);
    t = fmaf(d, t, p2);
    t = fmaf(d, t, -sx);
    return fmaf(d, t, cx);
}

#define FULLMASK 0xffffffffu

__global__ __launch_bounds__(32)
void recur_kernel(const float* __restrict__ Wf, const float* __restrict__ Wi,
                  const float* __restrict__ Wu, const float* __restrict__ Wo,
                  float* __restrict__ out)
{
    const int lane = threadIdx.x;
    const int u    = lane & 3;
    const int b    = blockIdx.x * 8 + (lane >> 2);

    // Whl[m][g] = W_gate_g[(128+m)*4 + u]
    float Whl[4][4];
    #pragma unroll
    for (int m = 0; m < 4; m++) {
        Whl[m][0] = Wf[(128 + m) * 4 + u];
        Whl[m][1] = Wi[(128 + m) * 4 + u];
        Whl[m][2] = Wu[(128 + m) * 4 + u];
        Whl[m][3] = Wo[(128 + m) * 4 + u];
    }
    const bool ge1 = (u >= 1);
    const bool ge2 = (u >= 2);
    const bool ge3 = (u >= 3);

    float h0 = 0.f, h1 = 0.f, h2 = 0.f, h3 = 0.f;
    float c  = 0.f;

    // per-lane stream: float4 pair {cos-quad, sin-quad}; per-t stride BATCH*8 float4
    const float4* xp = (const float4*)g_xproj + ((size_t)b * 4 + u) * 2;
    const size_t STRIDE = (size_t)BATCH * 8;
    float4 bufC[RDEPTH], bufS[RDEPTH];
    #pragma unroll
    for (int d = 0; d < RDEPTH; d++) {
        bufC[d] = xp[(size_t)d * STRIDE + 0];
        bufS[d] = xp[(size_t)d * STRIDE + 1];
    }

    #pragma unroll 4
    for (int t = 0; t < T_STEPS; t++) {
        const int slot = t & (RDEPTH - 1);
        float4 zc = bufC[slot];
        float4 zs = bufS[slot];
        bufC[slot] = xp[(size_t)(t + RDEPTH) * STRIDE + 0];
        bufS[slot] = xp[(size_t)(t + RDEPTH) * STRIDE + 1];

        // d_g = h . Whl[:,g] (tree), then cos via angle addition (FMA pipe only)
        float a, bb;
        a  = fmaf(h1, Whl[1][0], h0 * Whl[0][0]);
        bb = fmaf(h3, Whl[3][0], h2 * Whl[2][0]);
        float q0 = cos_aa(a + bb, zc.x, zs.x);
        a  = fmaf(h1, Whl[1][1], h0 * Whl[0][1]);
        bb = fmaf(h3, Whl[3][1], h2 * Whl[2][1]);
        float q1 = cos_aa(a + bb, zc.y, zs.y);
        a  = fmaf(h1, Whl[1][2], h0 * Whl[0][2]);
        bb = fmaf(h3, Whl[3][2], h2 * Whl[2][2]);
        float q2 = cos_aa(a + bb, zc.z, zs.z);
        a  = fmaf(h1, Whl[1][3], h0 * Whl[0][3]);
        bb = fmaf(h3, Whl[3][3], h2 * Whl[2][3]);
        float q3 = cos_aa(a + bb, zc.w, zs.w);

        // prefix product across the unit quad: 3 parallel index-shfls per gate,
        // then a 2-level predicated multiply tree
        {
            float s00 = __shfl_sync(FULLMASK, q0, 0, 4);
            float s01 = __shfl_sync(FULLMASK, q0, 1, 4);
            float s02 = __shfl_sync(FULLMASK, q0, 2, 4);
            float s10 = __shfl_sync(FULLMASK, q1, 0, 4);
            float s11 = __shfl_sync(FULLMASK, q1, 1, 4);
            float s12 = __shfl_sync(FULLMASK, q1, 2, 4);
            float s20 = __shfl_sync(FULLMASK, q2, 0, 4);
            float s21 = __shfl_sync(FULLMASK, q2, 1, 4);
            float s22 = __shfl_sync(FULLMASK, q2, 2, 4);
            float s30 = __shfl_sync(FULLMASK, q3, 0, 4);
            float s31 = __shfl_sync(FULLMASK, q3, 1, 4);
            float s32 = __shfl_sync(FULLMASK, q3, 2, 4);
            float m0 = ge1 ? s00 : 1.0f; if (ge2) m0 *= s01;
            float m1 = ge1 ? s10 : 1.0f; if (ge2) m1 *= s11;
            float m2 = ge1 ? s20 : 1.0f; if (ge2) m2 *= s21;
            float m3 = ge1 ? s30 : 1.0f; if (ge2) m3 *= s31;
            q0 *= m0; if (ge3) q0 *= s02;
            q1 *= m1; if (ge3) q1 *= s12;
            q2 *= m2; if (ge3) q2 *= s22;
            q3 *= m3; if (ge3) q3 *= s32;
        }

        // activations: f,i,o on FMA pipe; g via MUFU tanh (overlaps sigp chains)
        float f  = sigp(q0);
        float i  = sigp(q1);
        float gg = tanh_a(q2);
        float o  = sigp(q3);

        c = fmaf(f, c, i * gg);
        float hu = o * tanh_a(c);

        out[((size_t)t * BATCH + b) * 4 + u] = hu;

        // broadcast h within the 4-lane group
        h0 = __shfl_sync(FULLMASK, hu, 0, 4);
        h1 = __shfl_sync(FULLMASK, hu, 1, 4);
        h2 = __shfl_sync(FULLMASK, hu, 2, 4);
        h3 = __shfl_sync(FULLMASK, hu, 3, 4);
    }

    // hx, cx appended after outputs
    float hx = (u == 0) ? h0 : (u == 1) ? h1 : (u == 2) ? h2 : h3;
    out[(size_t)T_STEPS * BATCH * 4 + (size_t)b * 4 + u]                     = hx;
    out[(size_t)T_STEPS * BATCH * 4 + (size_t)BATCH * 4 + (size_t)b * 4 + u] = c;
}

// ---------------------------------------------------------------------------
extern "C" void kernel_launch(void* const* d_in, const int* in_sizes, int n_in,
                              void* d_out, int out_size)
{
    (void)in_sizes; (void)n_in; (void)out_size;
    const float* x   = (const float*)d_in[0];
    const float* Wf  = (const float*)d_in[1];
    const float* bf  = (const float*)d_in[2];
    const float* thf = (const float*)d_in[3];
    const float* Wi  = (const float*)d_in[4];
    const float* bi  = (const float*)d_in[5];
    const float* thi = (const float*)d_in[6];
    const float* Wu  = (const float*)d_in[7];
    const float* bu  = (const float*)d_in[8];
    const float* thu = (const float*)d_in[9];
    const float* Wo  = (const float*)d_in[10];
    const float* bo  = (const float*)d_in[11];
    const float* tho = (const float*)d_in[12];
    float* out = (float*)d_out;

    proj_kernel<<<(T_STEPS * BATCH) / TILE_ROWS, PROJ_THREADS>>>(
        x, Wf, bf, thf, Wi, bi, thi, Wu, bu, thu, Wo, bo, tho);
    recur_kernel<<<BATCH / 8, 32>>>(Wf, Wi, Wu, Wo, out);
}

// round 12
// speedup vs baseline: 1.2235x; 1.2235x over previous
#include <cuda_runtime.h>

#define T_STEPS 2048
#define BATCH   256
#define DIN     128
#define NG      16      // scratch layout k = u*4 + g
#define RDEPTH  4

#define RECUR_BLOCKS 32
#define PROJ_TILES   (T_STEPS * BATCH / 64)   // 8192
#define FUSED_THREADS 256

// Scratch: x-part projections (+bias+theta folded), layout [t][b][u*4+g]
// Over-allocated by RDEPTH steps so the recurrence prefetch needs no bounds check.
__device__ float g_xproj[(T_STEPS + RDEPTH) * BATCH * NG];
// per-t completion counters (4 proj tiles per t); tail pre-set to "done"
__device__ int g_done[T_STEPS + 16];

// ---------------------------------------------------------------------------
__global__ void clear_kernel()
{
    int i = blockIdx.x * blockDim.x + threadIdx.x;
    if (i < T_STEPS + 16)
        g_done[i] = (i < T_STEPS) ? 0 : 4;
}

// ---------------------------------------------------------------------------
// helpers
// ---------------------------------------------------------------------------
__device__ __forceinline__ float tanh_a(float x) {
    float y;
    asm("tanh.approx.f32 %0, %1;" : "=f"(y) : "f"(x));
    return y;
}
// sigmoid on [-1,1] via odd Taylor poly (err <= ~3e-6): fixed-latency FMA chain
__device__ __forceinline__ float sigp(float xv) {
    float x2 = xv * xv;
    float t = fmaf(x2, 2.135765e-5f, -2.1081349e-4f);
    t = fmaf(x2, t, 2.0833333e-3f);
    t = fmaf(x2, t, -2.0833333e-2f);
    t = fmaf(x2, t, 0.25f);
    return fmaf(xv, t, 0.5f);
}

#define FULLMASK 0xffffffffu

// ---------------------------------------------------------------------------
// Fused kernel: blocks [0,32) = recurrence (warp 7 only); rest = projection
// ---------------------------------------------------------------------------
__global__ __launch_bounds__(FUSED_THREADS)
void fused_kernel(const float* __restrict__ x,
                  const float* __restrict__ Wf, const float* __restrict__ bf, const float* __restrict__ thf,
                  const float* __restrict__ Wi, const float* __restrict__ bi, const float* __restrict__ thi,
                  const float* __restrict__ Wu, const float* __restrict__ bu, const float* __restrict__ thu,
                  const float* __restrict__ Wo, const float* __restrict__ bo, const float* __restrict__ tho,
                  float* __restrict__ out)
{
    const int tid = threadIdx.x;

    if (blockIdx.x >= RECUR_BLOCKS) {
        // ----------------------- projection tile -----------------------
        __shared__ float xs[64][132];
        __shared__ float ws[DIN][NG];          // ws[j][u*4+g]
        __shared__ float bt[NG];

        const long tileIdx = blockIdx.x - RECUR_BLOCKS;
        const long rowBase = tileIdx * 64;

        const float4* x4 = (const float4*)x + rowBase * (DIN / 4);
        #pragma unroll
        for (int i = tid; i < 64 * (DIN / 4); i += FUSED_THREADS) {
            float4 v = x4[i];
            int row = i >> 5;
            int c4  = i & 31;
            *(float4*)&xs[row][c4 * 4] = v;
        }
        for (int i = tid; i < DIN * NG; i += FUSED_THREADS) {
            int j = i >> 4, k = i & 15;
            int u = k >> 2, g = k & 3;
            const float* W = (g == 0) ? Wf : (g == 1) ? Wi : (g == 2) ? Wu : Wo;
            ws[j][k] = W[j * 4 + u];
        }
        if (tid < NG) {
            int u = tid >> 2, g = tid & 3;
            const float* b  = (g == 0) ? bf  : (g == 1) ? bi  : (g == 2) ? bu  : bo;
            const float* th = (g == 0) ? thf : (g == 1) ? thi : (g == 2) ? thu : tho;
            bt[tid] = b[u] + th[u];
        }
        __syncthreads();

        const int r  = tid & 63;
        const int kg = tid >> 6;
        float a0 = 0.f, a1 = 0.f, a2 = 0.f, a3 = 0.f;

        #pragma unroll
        for (int jj = 0; jj < DIN / 4; jj++) {
            float4 xv = *(const float4*)&xs[r][jj * 4];
            float4 w0 = *(const float4*)&ws[jj * 4 + 0][kg * 4];
            float4 w1 = *(const float4*)&ws[jj * 4 + 1][kg * 4];
            float4 w2 = *(const float4*)&ws[jj * 4 + 2][kg * 4];
            float4 w3 = *(const float4*)&ws[jj * 4 + 3][kg * 4];
            a0 = fmaf(xv.x, w0.x, fmaf(xv.y, w1.x, fmaf(xv.z, w2.x, fmaf(xv.w, w3.x, a0))));
            a1 = fmaf(xv.x, w0.y, fmaf(xv.y, w1.y, fmaf(xv.z, w2.y, fmaf(xv.w, w3.y, a1))));
            a2 = fmaf(xv.x, w0.z, fmaf(xv.y, w1.z, fmaf(xv.z, w2.z, fmaf(xv.w, w3.z, a2))));
            a3 = fmaf(xv.x, w0.w, fmaf(xv.y, w1.w, fmaf(xv.z, w2.w, fmaf(xv.w, w3.w, a3))));
        }
        float4 o;
        o.x = a0 + bt[kg * 4 + 0];
        o.y = a1 + bt[kg * 4 + 1];
        o.z = a2 + bt[kg * 4 + 2];
        o.w = a3 + bt[kg * 4 + 3];
        *(float4*)&g_xproj[(rowBase + r) * NG + kg * 4] = o;

        // publish: all stores visible, then bump this t's tile counter
        __threadfence();
        __syncthreads();
        if (tid == 0)
            atomicAdd(&g_done[(int)(rowBase >> 8)], 1);
        return;
    }

    // --------------------------- recurrence ---------------------------
    if (tid < 224) return;                 // warp 7 only (highest wid priority)
    const int lane = tid & 31;
    const int u    = lane & 3;
    const int b    = blockIdx.x * 8 + (lane >> 2);

    // Whl[m][g] = W_gate_g[(128+m)*4 + u]
    float Whl[4][4];
    #pragma unroll
    for (int m = 0; m < 4; m++) {
        Whl[m][0] = Wf[(128 + m) * 4 + u];
        Whl[m][1] = Wi[(128 + m) * 4 + u];
        Whl[m][2] = Wu[(128 + m) * 4 + u];
        Whl[m][3] = Wo[(128 + m) * 4 + u];
    }
    const bool ge1 = (u >= 1);
    const bool ge2 = (u >= 2);
    const bool ge3 = (u >= 3);

    float h0 = 0.f, h1 = 0.f, h2 = 0.f, h3 = 0.f;
    float c  = 0.f;

    const float4* xp = (const float4*)g_xproj + ((size_t)b * 4 + u);
    float4 buf[RDEPTH];
    int    fbuf[RDEPTH];
    #pragma unroll
    for (int d = 0; d < RDEPTH; d++) {
        while (*(volatile const int*)&g_done[d] != 4) { }
        buf[d]  = xp[(size_t)d * (BATCH * 4)];
        fbuf[d] = *(volatile const int*)&g_done[d + RDEPTH];
    }

    #pragma unroll 4
    for (int t = 0; t < T_STEPS; t++) {
        const int slot = t & (RDEPTH - 1);

        // verify flag for t+RDEPTH (prefetched 4 steps ago); rare spin if late
        if (fbuf[slot] != 4) {
            while (*(volatile const int*)&g_done[t + RDEPTH] != 4) { }
        }

        float4 zx = buf[slot];
        buf[slot]  = xp[(size_t)(t + RDEPTH) * (BATCH * 4)];
        fbuf[slot] = *(volatile const int*)&g_done[t + 2 * RDEPTH];

        // z_g = zx_g + h . Whl[:,g]  (tree form) then cos
        float a, bb;
        a  = fmaf(h1, Whl[1][0], fmaf(h0, Whl[0][0], zx.x));
        bb = fmaf(h3, Whl[3][0], h2 * Whl[2][0]);
        float q0 = __cosf(a + bb);
        a  = fmaf(h1, Whl[1][1], fmaf(h0, Whl[0][1], zx.y));
        bb = fmaf(h3, Whl[3][1], h2 * Whl[2][1]);
        float q1 = __cosf(a + bb);
        a  = fmaf(h1, Whl[1][2], fmaf(h0, Whl[0][2], zx.z));
        bb = fmaf(h3, Whl[3][2], h2 * Whl[2][2]);
        float q2 = __cosf(a + bb);
        a  = fmaf(h1, Whl[1][3], fmaf(h0, Whl[0][3], zx.w));
        bb = fmaf(h3, Whl[3][3], h2 * Whl[2][3]);
        float q3 = __cosf(a + bb);

        // prefix product across the unit quad: 3 parallel index-shfls per gate,
        // then a 2-level predicated multiply tree
        {
            float s00 = __shfl_sync(FULLMASK, q0, 0, 4);
            float s01 = __shfl_sync(FULLMASK, q0, 1, 4);
            float s02 = __shfl_sync(FULLMASK, q0, 2, 4);
            float s10 = __shfl_sync(FULLMASK, q1, 0, 4);
            float s11 = __shfl_sync(FULLMASK, q1, 1, 4);
            float s12 = __shfl_sync(FULLMASK, q1, 2, 4);
            float s20 = __shfl_sync(FULLMASK, q2, 0, 4);
            float s21 = __shfl_sync(FULLMASK, q2, 1, 4);
            float s22 = __shfl_sync(FULLMASK, q2, 2, 4);
            float s30 = __shfl_sync(FULLMASK, q3, 0, 4);
            float s31 = __shfl_sync(FULLMASK, q3, 1, 4);
            float s32 = __shfl_sync(FULLMASK, q3, 2, 4);
            float m0 = ge1 ? s00 : 1.0f; if (ge2) m0 *= s01;
            float m1 = ge1 ? s10 : 1.0f; if (ge2) m1 *= s11;
            float m2 = ge1 ? s20 : 1.0f; if (ge2) m2 *= s21;
            float m3 = ge1 ? s30 : 1.0f; if (ge2) m3 *= s31;
            q0 *= m0; if (ge3) q0 *= s02;
            q1 *= m1; if (ge3) q1 *= s12;
            q2 *= m2; if (ge3) q2 *= s22;
            q3 *= m3; if (ge3) q3 *= s32;
        }

        // activations: f,i,o on FMA pipe; g via MUFU tanh (overlaps sigp chains)
        float f  = sigp(q0);
        float i  = sigp(q1);
        float gg = tanh_a(q2);
        float o  = sigp(q3);

        c = fmaf(f, c, i * gg);
        float hu = o * tanh_a(c);

        out[((size_t)t * BATCH + b) * 4 + u] = hu;

        // broadcast h within the 4-lane group
        h0 = __shfl_sync(FULLMASK, hu, 0, 4);
        h1 = __shfl_sync(FULLMASK, hu, 1, 4);
        h2 = __shfl_sync(FULLMASK, hu, 2, 4);
        h3 = __shfl_sync(FULLMASK, hu, 3, 4);
    }

    // hx, cx appended after outputs
    float hx = (u == 0) ? h0 : (u == 1) ? h1 : (u == 2) ? h2 : h3;
    out[(size_t)T_STEPS * BATCH * 4 + (size_t)b * 4 + u]                     = hx;
    out[(size_t)T_STEPS * BATCH * 4 + (size_t)BATCH * 4 + (size_t)b * 4 + u] = c;
}

// ---------------------------------------------------------------------------
extern "C" void kernel_launch(void* const* d_in, const int* in_sizes, int n_in,
                              void* d_out, int out_size)
{
    (void)in_sizes; (void)n_in; (void)out_size;
    const float* x   = (const float*)d_in[0];
    const float* Wf  = (const float*)d_in[1];
    const float* bf  = (const float*)d_in[2];
    const float* thf = (const float*)d_in[3];
    const float* Wi  = (const float*)d_in[4];
    const float* bi  = (const float*)d_in[5];
    const float* thi = (const float*)d_in[6];
    const float* Wu  = (const float*)d_in[7];
    const float* bu  = (const float*)d_in[8];
    const float* thu = (const float*)d_in[9];
    const float* Wo  = (const float*)d_in[10];
    const float* bo  = (const float*)d_in[11];
    const float* tho = (const float*)d_in[12];
    float* out = (float*)d_out;

    clear_kernel<<<(T_STEPS + 16 + 255) / 256, 256>>>();
    fused_kernel<<<RECUR_BLOCKS + PROJ_TILES, FUSED_THREADS>>>(
        x, Wf, bf, thf, Wi, bi, thi, Wu, bu, thu, Wo, bo, tho, out);
}